// round 8
// baseline (speedup 1.0000x reference)
#include <cuda_runtime.h>
#include <cuda_fp16.h>

#define Nn   50000
#define Ee   800000
#define F_IN 128
#define HID  64
#define Ll   3
#define Gg   512
#define BN_EPS 1e-5f
#define INVN (1.0f / 50000.0f)

#define EDGE_BLOCKS  ((Ee + 255) / 256)            // 3125
#define STAT_BLOCKS  256
#define GEMM_BLOCKS  ((Nn + 127) / 128)            // 391
#define GATHER_GRID  ((Nn + 15) / 16)              // 3125
#define SCAN_T   512
#define SCAN_E   2048
#define SCAN_NB  ((Nn + SCAN_E - 1) / SCAN_E)      // 25

// ---------------- scratch (static device arrays; zero-initialized) ---------
__device__ __align__(16) float  g_h[Nn * HID];     // activations (post-relu)
__device__ __align__(16) __half g_zh[Nn * HID];    // dis-prescaled z, fp16
__device__ __align__(16) float  g_sum[F_IN];       // x stats (zero invariant)
__device__ __align__(16) float  g_sumsq[F_IN];
__device__ __align__(16) float  g_sl[Ll][2][HID];  // layer stats (zero inv.)
__device__ int    g_degout[Nn];                    // zero invariant
__device__ int    g_degin[Nn];                     // zero invariant
__device__ float  g_dis[Nn];
__device__ int    g_off[Nn + 1];
__device__ int    g_cursor[Nn];
__device__ int    g_csr[Ee];
__device__ int    g_bsum[SCAN_NB];
__device__ int    g_bbase[SCAN_NB];
__device__ int    g_ctr;                           // zero invariant

// ---------------- helpers ----------------------------------------------------
__device__ __forceinline__ void red_add_v4(float* addr, float4 v) {
    asm volatile("red.global.add.v4.f32 [%0], {%1, %2, %3, %4};"
                 :: "l"(addr), "f"(v.x), "f"(v.y), "f"(v.z), "f"(v.w)
                 : "memory");
}

__device__ __forceinline__ float4 h4_to_f4(uint2 u) {
    __half2 a = *(__half2*)&u.x;
    __half2 b = *(__half2*)&u.y;
    float2 fa = __half22float2(a);
    float2 fb = __half22float2(b);
    return make_float4(fa.x, fa.y, fb.x, fb.y);
}

// ---------------- chain B: edge degree count ---------------------------------
__global__ void __launch_bounds__(256)
count_kernel(const int* __restrict__ src, const int* __restrict__ dst) {
    int e = blockIdx.x * blockDim.x + threadIdx.x;
    if (e < Ee) {
        atomicAdd(&g_degout[src[e]], 1);
        atomicAdd(&g_degin[dst[e]], 1);
    }
}

// ---------------- chain A: x column stats ------------------------------------
__global__ void __launch_bounds__(256)
stats_x_kernel(const float* __restrict__ x) {
    int t = threadIdx.x;
    int col = t & 127, half = t >> 7;
    float s = 0.f, ss = 0.f;
    for (int r = blockIdx.x * 2 + half; r < Nn; r += STAT_BLOCKS * 2) {
        float v = x[(long)r * F_IN + col];
        s += v; ss += v * v;
    }
    __shared__ float sh0[256], sh1[256];
    sh0[t] = s; sh1[t] = ss;
    __syncthreads();
    if (half == 0) {
        s += sh0[128 + col]; ss += sh1[128 + col];
        atomicAdd(&g_sum[col], s);
        atomicAdd(&g_sumsq[col], ss);
    }
}

// ---------------- scan: block sums + last-block serial base scan -------------
__global__ void scan12_kernel() {
    __shared__ int sh[SCAN_T];
    int t = threadIdx.x, b = blockIdx.x;
    int s = 0;
    #pragma unroll
    for (int j = 0; j < 4; j++) {
        int i = b * SCAN_E + t + j * SCAN_T;
        if (i < Nn) s += g_degin[i];
    }
    sh[t] = s; __syncthreads();
    for (int o = SCAN_T / 2; o > 0; o >>= 1) {
        if (t < o) sh[t] += sh[t + o];
        __syncthreads();
    }
    if (t == 0) {
        g_bsum[b] = sh[0];
        __threadfence();
        if (atomicAdd(&g_ctr, 1) == SCAN_NB - 1) {
            g_ctr = 0;
            int acc = 0;
            for (int j = 0; j < SCAN_NB; j++) {
                g_bbase[j] = acc;
                acc += __ldcg(&g_bsum[j]);
            }
            g_off[Nn] = acc;
        }
    }
}

__global__ void scan3_kernel() {   // local scan + cursor + dis
    __shared__ int sh[SCAN_T];
    int t = threadIdx.x, b = blockIdx.x;
    int base = b * SCAN_E + t * 4;
    int d0 = 0, d1 = 0, d2 = 0, d3 = 0;
    if (base + 0 < Nn) d0 = g_degin[base + 0];
    if (base + 1 < Nn) d1 = g_degin[base + 1];
    if (base + 2 < Nn) d2 = g_degin[base + 2];
    if (base + 3 < Nn) d3 = g_degin[base + 3];
    int tsum = d0 + d1 + d2 + d3;
    sh[t] = tsum; __syncthreads();
    for (int o = 1; o < SCAN_T; o <<= 1) {
        int v = (t >= o) ? sh[t - o] : 0;
        __syncthreads();
        sh[t] += v;
        __syncthreads();
    }
    int excl = sh[t] - tsum + g_bbase[b];
    int o0 = excl, o1 = o0 + d0, o2 = o1 + d1, o3 = o2 + d2;
    if (base + 0 < Nn) {
        g_off[base + 0] = o0; g_cursor[base + 0] = o0;
        g_dis[base + 0] = rsqrtf((float)(g_degout[base + 0] + 1));
    }
    if (base + 1 < Nn) {
        g_off[base + 1] = o1; g_cursor[base + 1] = o1;
        g_dis[base + 1] = rsqrtf((float)(g_degout[base + 1] + 1));
    }
    if (base + 2 < Nn) {
        g_off[base + 2] = o2; g_cursor[base + 2] = o2;
        g_dis[base + 2] = rsqrtf((float)(g_degout[base + 2] + 1));
    }
    if (base + 3 < Nn) {
        g_off[base + 3] = o3; g_cursor[base + 3] = o3;
        g_dis[base + 3] = rsqrtf((float)(g_degout[base + 3] + 1));
    }
}

// ---------------- fill CSR + restore deg zero invariant ---------------------
__global__ void __launch_bounds__(256)
fill_kernel(const int* __restrict__ src, const int* __restrict__ dst) {
    int e = blockIdx.x * blockDim.x + threadIdx.x;
    if (e < Ee) {
        int pos = atomicAdd(&g_cursor[dst[e]], 1);
        g_csr[pos] = src[e];
    }
    if (e < Nn) { g_degin[e] = 0; g_degout[e] = 0; }
}

// ---------------- GEMM with inline BN fold -----------------------------------
// Prologue (per block, redundant): s = gamma*rsqrt(var+eps), t = beta - mu*s,
// c = t@W (+blin). W tile staged pre-scaled by s. FEAT: h=relu(.), stats out.
// LAYER: g_zh = fp16(dis_row * .).
template <int K, bool FEAT>
__global__ void __launch_bounds__(256, 2)
gemm_kernel(const float* __restrict__ A,
            const float* __restrict__ gamma, const float* __restrict__ beta,
            const float* __restrict__ W, const float* __restrict__ blin,
            const float* __restrict__ sums, const float* __restrict__ sqs) {
    extern __shared__ float smem[];
    float* As  = smem;                 // 128*64
    float* Wsm = As + 128 * 64;        // 64*64
    float* s_s = Wsm + 64 * 64;        // K
    float* s_t = s_s + K;              // K
    float* s_c = s_t + K;              // 64
    const int t  = threadIdx.x;
    const int tx = t & 15;
    const int ty = t >> 4;
    const int rowBase = blockIdx.x * 128;

    // ---- inline fold ----
    if (t < K) {
        float mu  = sums[t] * INVN;
        float var = fmaxf(sqs[t] * INVN - mu * mu, 0.f);
        float sc  = gamma[t] * rsqrtf(var + BN_EPS);
        s_s[t] = sc;
        s_t[t] = beta[t] - mu * sc;
    }
    __syncthreads();
    if (t < HID) {
        float c = blin ? blin[t] : 0.f;
        #pragma unroll 8
        for (int k = 0; k < K; k++) c += s_t[k] * W[k * HID + t];
        s_c[t] = c;
    }

    float4 acc[8];
    #pragma unroll
    for (int i = 0; i < 8; i++) acc[i] = make_float4(0.f, 0.f, 0.f, 0.f);

    for (int kt = 0; kt < K; kt += 64) {
        #pragma unroll
        for (int i = t; i < 128 * 16; i += 256) {
            int r = i >> 4, c4 = i & 15;
            int gr = rowBase + r;
            float4 v = {0,0,0,0};
            if (gr < Nn) v = *(const float4*)(A + (long)gr * K + kt + 4 * c4);
            ((float4*)As)[i] = v;
        }
        __syncthreads();   // also covers first-tile s_s availability
        #pragma unroll
        for (int i = t; i < 64 * 16; i += 256) {
            int r = i >> 4, c4 = i & 15;
            float sc = s_s[kt + r];
            float4 w = *(const float4*)(W + (long)(kt + r) * HID + 4 * c4);
            w.x *= sc; w.y *= sc; w.z *= sc; w.w *= sc;
            ((float4*)Wsm)[i] = w;
        }
        __syncthreads();

        #pragma unroll
        for (int k4 = 0; k4 < 16; k4++) {
            float4 w0 = ((const float4*)Wsm)[(4 * k4 + 0) * 16 + tx];
            float4 w1 = ((const float4*)Wsm)[(4 * k4 + 1) * 16 + tx];
            float4 w2 = ((const float4*)Wsm)[(4 * k4 + 2) * 16 + tx];
            float4 w3 = ((const float4*)Wsm)[(4 * k4 + 3) * 16 + tx];
            #pragma unroll
            for (int i = 0; i < 8; i++) {
                float4 a = ((const float4*)As)[(8 * ty + i) * 16 + k4];
                acc[i].x += a.x * w0.x; acc[i].y += a.x * w0.y;
                acc[i].z += a.x * w0.z; acc[i].w += a.x * w0.w;
                acc[i].x += a.y * w1.x; acc[i].y += a.y * w1.y;
                acc[i].z += a.y * w1.z; acc[i].w += a.y * w1.w;
                acc[i].x += a.z * w2.x; acc[i].y += a.z * w2.y;
                acc[i].z += a.z * w2.z; acc[i].w += a.z * w2.w;
                acc[i].x += a.w * w3.x; acc[i].y += a.w * w3.y;
                acc[i].z += a.w * w3.z; acc[i].w += a.w * w3.w;
            }
        }
        __syncthreads();
    }

    float4 cv = *(const float4*)(s_c + 4 * tx);
    float4 ls = {0,0,0,0}, lq = {0,0,0,0};
    #pragma unroll
    for (int i = 0; i < 8; i++) {
        int gr = rowBase + 8 * ty + i;
        if (gr >= Nn) continue;
        float4 v = acc[i];
        v.x += cv.x; v.y += cv.y; v.z += cv.z; v.w += cv.w;
        if (FEAT) {
            v.x = fmaxf(v.x, 0.f); v.y = fmaxf(v.y, 0.f);
            v.z = fmaxf(v.z, 0.f); v.w = fmaxf(v.w, 0.f);
            *(float4*)(g_h + (long)gr * 64 + 4 * tx) = v;
            ls.x += v.x; ls.y += v.y; ls.z += v.z; ls.w += v.w;
            lq.x += v.x * v.x; lq.y += v.y * v.y;
            lq.z += v.z * v.z; lq.w += v.w * v.w;
        } else {
            float di = __ldg(g_dis + gr);
            __half2 p0 = __floats2half2_rn(di * v.x, di * v.y);
            __half2 p1 = __floats2half2_rn(di * v.z, di * v.w);
            uint2 u;
            u.x = *(unsigned*)&p0;
            u.y = *(unsigned*)&p1;
            *(uint2*)(g_zh + (long)gr * 64 + 4 * tx) = u;
        }
    }
    if (FEAT) {   // per-column partial stats -> g_sl[0]
        __syncthreads();
        ((float4*)As)[t]       = ls;
        ((float4*)As)[256 + t] = lq;
        __syncthreads();
        if (ty == 0) {
            #pragma unroll
            for (int j = 1; j < 16; j++) {
                float4 a = ((float4*)As)[j * 16 + tx];
                float4 b = ((float4*)As)[256 + j * 16 + tx];
                ls.x += a.x; ls.y += a.y; ls.z += a.z; ls.w += a.w;
                lq.x += b.x; lq.y += b.y; lq.z += b.z; lq.w += b.w;
            }
            red_add_v4(&g_sl[0][0][4 * tx], ls);
            red_add_v4(&g_sl[0][1][4 * tx], lq);
        }
    }
}

// ---------------- CSR gather aggregation (fp16 zs, pre-scaled) --------------
// MODE 0: h -> g_h, stats -> (ssum, ssq).  MODE 1: pool into gout; block 0
// re-zeroes all stats accumulators (replay invariant).
template <int MODE>
__global__ void __launch_bounds__(256)
gather_kernel(const float* __restrict__ bias,
              const int* __restrict__ batch,
              float* __restrict__ gout,
              float* __restrict__ ssum, float* __restrict__ ssq) {
    const int t    = threadIdx.x;
    const int c    = t & 15;
    const int slot = t >> 4;
    const int i    = blockIdx.x * 16 + slot;

    if (MODE == 1 && blockIdx.x == 0) {
        if (t < 128) { g_sum[t] = 0.f; g_sumsq[t] = 0.f; }
        for (int j = t; j < Ll * 2 * HID; j += 256)
            ((float*)g_sl)[j] = 0.f;
    }

    float4 b4 = *(const float4*)(bias + 4 * c);
    float4 ls = {0,0,0,0}, lq = {0,0,0,0};

    if (i < Nn) {
        int st = __ldg(g_off + i), en = __ldg(g_off + i + 1);
        float di = __ldg(g_dis + i);
        const __half* zb = g_zh;
        float4 acc = h4_to_f4(__ldg((const uint2*)(zb + (long)i * 64) + c));
        int e = st;
        for (; e + 7 < en; e += 8) {
            int s0 = __ldg(g_csr + e + 0);
            int s1 = __ldg(g_csr + e + 1);
            int s2 = __ldg(g_csr + e + 2);
            int s3 = __ldg(g_csr + e + 3);
            int s4 = __ldg(g_csr + e + 4);
            int s5 = __ldg(g_csr + e + 5);
            int s6 = __ldg(g_csr + e + 6);
            int s7 = __ldg(g_csr + e + 7);
            uint2 u0 = __ldg((const uint2*)(zb + (long)s0 * 64) + c);
            uint2 u1 = __ldg((const uint2*)(zb + (long)s1 * 64) + c);
            uint2 u2 = __ldg((const uint2*)(zb + (long)s2 * 64) + c);
            uint2 u3 = __ldg((const uint2*)(zb + (long)s3 * 64) + c);
            uint2 u4 = __ldg((const uint2*)(zb + (long)s4 * 64) + c);
            uint2 u5 = __ldg((const uint2*)(zb + (long)s5 * 64) + c);
            uint2 u6 = __ldg((const uint2*)(zb + (long)s6 * 64) + c);
            uint2 u7 = __ldg((const uint2*)(zb + (long)s7 * 64) + c);
            float4 v0 = h4_to_f4(u0), v1 = h4_to_f4(u1);
            float4 v2 = h4_to_f4(u2), v3 = h4_to_f4(u3);
            float4 v4 = h4_to_f4(u4), v5 = h4_to_f4(u5);
            float4 v6 = h4_to_f4(u6), v7 = h4_to_f4(u7);
            acc.x += (v0.x + v1.x) + (v2.x + v3.x) + (v4.x + v5.x) + (v6.x + v7.x);
            acc.y += (v0.y + v1.y) + (v2.y + v3.y) + (v4.y + v5.y) + (v6.y + v7.y);
            acc.z += (v0.z + v1.z) + (v2.z + v3.z) + (v4.z + v5.z) + (v6.z + v7.z);
            acc.w += (v0.w + v1.w) + (v2.w + v3.w) + (v4.w + v5.w) + (v6.w + v7.w);
        }
        for (; e + 3 < en; e += 4) {
            int s0 = __ldg(g_csr + e + 0);
            int s1 = __ldg(g_csr + e + 1);
            int s2 = __ldg(g_csr + e + 2);
            int s3 = __ldg(g_csr + e + 3);
            uint2 u0 = __ldg((const uint2*)(zb + (long)s0 * 64) + c);
            uint2 u1 = __ldg((const uint2*)(zb + (long)s1 * 64) + c);
            uint2 u2 = __ldg((const uint2*)(zb + (long)s2 * 64) + c);
            uint2 u3 = __ldg((const uint2*)(zb + (long)s3 * 64) + c);
            float4 v0 = h4_to_f4(u0), v1 = h4_to_f4(u1);
            float4 v2 = h4_to_f4(u2), v3 = h4_to_f4(u3);
            acc.x += (v0.x + v1.x) + (v2.x + v3.x);
            acc.y += (v0.y + v1.y) + (v2.y + v3.y);
            acc.z += (v0.z + v1.z) + (v2.z + v3.z);
            acc.w += (v0.w + v1.w) + (v2.w + v3.w);
        }
        for (; e < en; e++) {
            int s = __ldg(g_csr + e);
            float4 v = h4_to_f4(__ldg((const uint2*)(zb + (long)s * 64) + c));
            acc.x += v.x; acc.y += v.y; acc.z += v.z; acc.w += v.w;
        }
        float4 h;
        h.x = fmaxf(di * acc.x + b4.x, 0.f);
        h.y = fmaxf(di * acc.y + b4.y, 0.f);
        h.z = fmaxf(di * acc.z + b4.z, 0.f);
        h.w = fmaxf(di * acc.w + b4.w, 0.f);
        if (MODE == 0) {
            *(float4*)(g_h + (long)i * 64 + 4 * c) = h;
            ls = h;
            lq.x = h.x * h.x; lq.y = h.y * h.y;
            lq.z = h.z * h.z; lq.w = h.w * h.w;
        } else {
            int g = __ldg(batch + i);
            red_add_v4(gout + (long)g * 64 + 4 * c, h);
        }
    }

    if (MODE == 0) {
        __shared__ float4 shS[256], shQ[256];
        shS[t] = ls; shQ[t] = lq;
        __syncthreads();
        if (slot == 0) {
            #pragma unroll
            for (int j = 1; j < 16; j++) {
                float4 a = shS[j * 16 + c], b = shQ[j * 16 + c];
                ls.x += a.x; ls.y += a.y; ls.z += a.z; ls.w += a.w;
                lq.x += b.x; lq.y += b.y; lq.z += b.z; lq.w += b.w;
            }
            red_add_v4(ssum + 4 * c, ls);
            red_add_v4(ssq + 4 * c, lq);
        }
    }
}

// ---------------- host-side symbol resolution --------------------------------
static float* sym(const void* s) {
    float* p = nullptr;
    cudaGetSymbolAddress((void**)&p, s);
    return p;
}

// ---------------- launch ------------------------------------------------------
extern "C" void kernel_launch(void* const* d_in, const int* in_sizes, int n_in,
                              void* d_out, int out_size) {
    const float* x         = (const float*)d_in[0];
    const int*   ei        = (const int*)d_in[1];
    const int*   src       = ei;
    const int*   dst       = ei + Ee;
    const int*   batch     = (const int*)d_in[2];
    const float* bn_feat_g = (const float*)d_in[3];
    const float* bn_feat_b = (const float*)d_in[4];
    const float* W_feat    = (const float*)d_in[5];
    const float* b_feat    = (const float*)d_in[6];
    const float* bn_g      = (const float*)d_in[7];
    const float* bn_b      = (const float*)d_in[8];
    const float* Ws        = (const float*)d_in[9];
    const float* bs        = (const float*)d_in[10];
    float* gout = (float*)d_out;

    static const size_t SM_FEAT  = (128*64 + 64*64 + 2*F_IN + 64) * 4;
    static const size_t SM_LAYER = (128*64 + 64*64 + 2*HID  + 64) * 4;

    static cudaStream_t s2 = nullptr;
    static cudaEvent_t e0 = nullptr, eDis = nullptr, eCsr = nullptr;
    static float *pH, *pSum, *pSq, *pSl;
    if (!s2) {
        cudaStreamCreateWithFlags(&s2, cudaStreamNonBlocking);
        cudaEventCreateWithFlags(&e0,   cudaEventDisableTiming);
        cudaEventCreateWithFlags(&eDis, cudaEventDisableTiming);
        cudaEventCreateWithFlags(&eCsr, cudaEventDisableTiming);
        cudaFuncSetAttribute(gemm_kernel<F_IN, true>,
            cudaFuncAttributeMaxDynamicSharedMemorySize, (int)SM_FEAT);
        cudaFuncSetAttribute(gemm_kernel<HID, false>,
            cudaFuncAttributeMaxDynamicSharedMemorySize, (int)SM_LAYER);
        pH   = sym(g_h);
        pSum = sym(g_sum);
        pSq  = sym(g_sumsq);
        pSl  = sym(g_sl);
    }

    // ---- fork: chain B (CSR build + dis) on s2 ----
    cudaEventRecord(e0, 0);
    cudaStreamWaitEvent(s2, e0, 0);
    count_kernel<<<EDGE_BLOCKS, 256, 0, s2>>>(src, dst);
    scan12_kernel<<<SCAN_NB, SCAN_T, 0, s2>>>();
    scan3_kernel<<<SCAN_NB, SCAN_T, 0, s2>>>();
    cudaEventRecord(eDis, s2);                      // g_dis + g_off ready
    fill_kernel<<<EDGE_BLOCKS, 256, 0, s2>>>(src, dst);
    cudaEventRecord(eCsr, s2);                      // g_csr ready

    // ---- chain A on main stream ----
    stats_x_kernel<<<STAT_BLOCKS, 256>>>(x);
    gemm_kernel<F_IN, true><<<GEMM_BLOCKS, 256, SM_FEAT>>>(
        x, bn_feat_g, bn_feat_b, W_feat, b_feat, pSum, pSq);
    cudaMemsetAsync(gout, 0, (size_t)Gg * HID * sizeof(float));

    for (int i = 0; i < Ll; i++) {
        float* slot = pSl + (size_t)i * 2 * HID;
        if (i == 0) cudaStreamWaitEvent(0, eDis, 0);   // epilogue needs dis
        gemm_kernel<HID, false><<<GEMM_BLOCKS, 256, SM_LAYER>>>(
            pH, bn_g + i * HID, bn_b + i * HID,
            Ws + (long)i * HID * HID, nullptr, slot, slot + HID);
        if (i == 0) cudaStreamWaitEvent(0, eCsr, 0);   // gather needs CSR
        float* next = pSl + (size_t)(i + 1) * 2 * HID;
        if (i < Ll - 1)
            gather_kernel<0><<<GATHER_GRID, 256>>>(
                bs + i * HID, nullptr, nullptr, next, next + HID);
        else
            gather_kernel<1><<<GATHER_GRID, 256>>>(
                bs + i * HID, batch, gout, nullptr, nullptr);
    }
}

// round 9
// speedup vs baseline: 1.0006x; 1.0006x over previous
#include <cuda_runtime.h>
#include <cuda_fp16.h>

#define Nn   50000
#define Ee   800000
#define F_IN 128
#define HID  64
#define Ll   3
#define Gg   512
#define BN_EPS 1e-5f
#define INVN (1.0f / 50000.0f)

#define EDGE_BLOCKS  ((Ee + 255) / 256)            // 3125
#define STAT_BLOCKS  256
#define GEMM_BLOCKS  ((Nn + 127) / 128)            // 391
#define GATHER_GRID  ((Nn + 15) / 16)              // 3125
#define SCAN_T   512
#define SCAN_E   2048
#define SCAN_NB  ((Nn + SCAN_E - 1) / SCAN_E)      // 25

// ---------------- scratch (static device arrays; zero-initialized) ---------
__device__ __align__(16) float  g_h[Nn * HID];     // activations (post-relu)
__device__ __align__(16) __half g_zh[Nn * HID];    // dis-prescaled z, fp16
__device__ __align__(16) float  g_sum[F_IN];       // x stats (zero invariant)
__device__ __align__(16) float  g_sumsq[F_IN];
__device__ __align__(16) float  g_sl[Ll][2][HID];  // layer stats (zero inv.)
__device__ int      g_degout[Nn];                  // zero invariant
__device__ int      g_degin[Nn];                   // zero invariant
__device__ float    g_dis[Nn];
__device__ int      g_off[Nn + 1];
__device__ int      g_cursor[Nn];
__device__ int      g_csr[Ee];
__device__ unsigned g_pub[SCAN_NB];                // lookback (zero invariant)

// ---------------- helpers ----------------------------------------------------
__device__ __forceinline__ void pdl_entry() {
    cudaTriggerProgrammaticLaunchCompletion();
    cudaGridDependencySynchronize();
}

__device__ __forceinline__ void red_add_v4(float* addr, float4 v) {
    asm volatile("red.global.add.v4.f32 [%0], {%1, %2, %3, %4};"
                 :: "l"(addr), "f"(v.x), "f"(v.y), "f"(v.z), "f"(v.w)
                 : "memory");
}

__device__ __forceinline__ float4 h4_to_f4(uint2 u) {
    __half2 a = *(__half2*)&u.x;
    __half2 b = *(__half2*)&u.y;
    float2 fa = __half22float2(a);
    float2 fb = __half22float2(b);
    return make_float4(fa.x, fa.y, fb.x, fb.y);
}

// ---------------- chain B: edge degree count ---------------------------------
__global__ void __launch_bounds__(256)
count_kernel(const int* __restrict__ src, const int* __restrict__ dst) {
    pdl_entry();
    int e = blockIdx.x * blockDim.x + threadIdx.x;
    if (e < Ee) {
        atomicAdd(&g_degout[src[e]], 1);
        atomicAdd(&g_degin[dst[e]], 1);
    }
}

// ---------------- chain A: x column stats ------------------------------------
__global__ void __launch_bounds__(256)
stats_x_kernel(const float* __restrict__ x) {
    pdl_entry();
    int t = threadIdx.x;
    int col = t & 127, half = t >> 7;
    float s = 0.f, ss = 0.f;
    for (int r = blockIdx.x * 2 + half; r < Nn; r += STAT_BLOCKS * 2) {
        float v = x[(long)r * F_IN + col];
        s += v; ss += v * v;
    }
    __shared__ float sh0[256], sh1[256];
    sh0[t] = s; sh1[t] = ss;
    __syncthreads();
    if (half == 0) {
        s += sh0[128 + col]; ss += sh1[128 + col];
        atomicAdd(&g_sum[col], s);
        atomicAdd(&g_sumsq[col], ss);
    }
}

// ---------------- fused single-pass scan (decoupled lookback) + dis ---------
// 25 blocks, all co-resident. Publishes (agg | 0x80000000) to g_pub; lookback
// sums predecessors. g_pub reset to 0 by fill_kernel (replay invariant).
__global__ void __launch_bounds__(SCAN_T)
scan_dis_kernel() {
    pdl_entry();
    __shared__ int sh[SCAN_T];
    __shared__ int s_base;
    int t = threadIdx.x, b = blockIdx.x;
    int base = b * SCAN_E + t * 4;
    int d0 = 0, d1 = 0, d2 = 0, d3 = 0;
    if (base + 0 < Nn) d0 = g_degin[base + 0];
    if (base + 1 < Nn) d1 = g_degin[base + 1];
    if (base + 2 < Nn) d2 = g_degin[base + 2];
    if (base + 3 < Nn) d3 = g_degin[base + 3];
    int tsum = d0 + d1 + d2 + d3;
    sh[t] = tsum; __syncthreads();
    for (int o = 1; o < SCAN_T; o <<= 1) {      // Hillis-Steele inclusive
        int v = (t >= o) ? sh[t - o] : 0;
        __syncthreads();
        sh[t] += v;
        __syncthreads();
    }
    if (t == SCAN_T - 1)                        // publish block aggregate
        atomicExch(&g_pub[b], (unsigned)sh[t] | 0x80000000u);
    if (t == 0) {                               // lookback over predecessors
        int acc = 0;
        for (int j = 0; j < b; j++) {
            unsigned v;
            do { v = atomicAdd(&g_pub[j], 0u); } while (!(v & 0x80000000u));
            acc += (int)(v & 0x7fffffffu);
        }
        s_base = acc;
    }
    __syncthreads();
    int excl = sh[t] - tsum + s_base;
    int o0 = excl, o1 = o0 + d0, o2 = o1 + d1, o3 = o2 + d2;
    if (base + 0 < Nn) {
        g_off[base + 0] = o0; g_cursor[base + 0] = o0;
        g_dis[base + 0] = rsqrtf((float)(g_degout[base + 0] + 1));
    }
    if (base + 1 < Nn) {
        g_off[base + 1] = o1; g_cursor[base + 1] = o1;
        g_dis[base + 1] = rsqrtf((float)(g_degout[base + 1] + 1));
    }
    if (base + 2 < Nn) {
        g_off[base + 2] = o2; g_cursor[base + 2] = o2;
        g_dis[base + 2] = rsqrtf((float)(g_degout[base + 2] + 1));
    }
    if (base + 3 < Nn) {
        g_off[base + 3] = o3; g_cursor[base + 3] = o3;
        g_dis[base + 3] = rsqrtf((float)(g_degout[base + 3] + 1));
    }
    if (b == SCAN_NB - 1 && t == SCAN_T - 1)
        g_off[Nn] = s_base + sh[t];
}

// ---------------- fill CSR + restore zero invariants -------------------------
__global__ void __launch_bounds__(256)
fill_kernel(const int* __restrict__ src, const int* __restrict__ dst) {
    pdl_entry();
    int e = blockIdx.x * blockDim.x + threadIdx.x;
    if (e < Ee) {
        int pos = atomicAdd(&g_cursor[dst[e]], 1);
        g_csr[pos] = src[e];
    }
    if (e < Nn) { g_degin[e] = 0; g_degout[e] = 0; }
    if (e < SCAN_NB) g_pub[e] = 0;
}

// ---------------- GEMM with inline BN fold -----------------------------------
template <int K, bool FEAT>
__global__ void __launch_bounds__(256, 2)
gemm_kernel(const float* __restrict__ A,
            const float* __restrict__ gamma, const float* __restrict__ beta,
            const float* __restrict__ W, const float* __restrict__ blin,
            const float* __restrict__ sums, const float* __restrict__ sqs) {
    pdl_entry();
    extern __shared__ float smem[];
    float* As  = smem;                 // 128*64
    float* Wsm = As + 128 * 64;        // 64*64
    float* s_s = Wsm + 64 * 64;        // K
    float* s_t = s_s + K;              // K
    float* s_c = s_t + K;              // 64
    const int t  = threadIdx.x;
    const int tx = t & 15;
    const int ty = t >> 4;
    const int rowBase = blockIdx.x * 128;

    if (t < K) {
        float mu  = sums[t] * INVN;
        float var = fmaxf(sqs[t] * INVN - mu * mu, 0.f);
        float sc  = gamma[t] * rsqrtf(var + BN_EPS);
        s_s[t] = sc;
        s_t[t] = beta[t] - mu * sc;
    }
    __syncthreads();
    if (t < HID) {
        float c = blin ? blin[t] : 0.f;
        #pragma unroll 8
        for (int k = 0; k < K; k++) c += s_t[k] * W[k * HID + t];
        s_c[t] = c;
    }

    float4 acc[8];
    #pragma unroll
    for (int i = 0; i < 8; i++) acc[i] = make_float4(0.f, 0.f, 0.f, 0.f);

    for (int kt = 0; kt < K; kt += 64) {
        #pragma unroll
        for (int i = t; i < 128 * 16; i += 256) {
            int r = i >> 4, c4 = i & 15;
            int gr = rowBase + r;
            float4 v = {0,0,0,0};
            if (gr < Nn) v = *(const float4*)(A + (long)gr * K + kt + 4 * c4);
            ((float4*)As)[i] = v;
        }
        __syncthreads();
        #pragma unroll
        for (int i = t; i < 64 * 16; i += 256) {
            int r = i >> 4, c4 = i & 15;
            float sc = s_s[kt + r];
            float4 w = *(const float4*)(W + (long)(kt + r) * HID + 4 * c4);
            w.x *= sc; w.y *= sc; w.z *= sc; w.w *= sc;
            ((float4*)Wsm)[i] = w;
        }
        __syncthreads();

        #pragma unroll
        for (int k4 = 0; k4 < 16; k4++) {
            float4 w0 = ((const float4*)Wsm)[(4 * k4 + 0) * 16 + tx];
            float4 w1 = ((const float4*)Wsm)[(4 * k4 + 1) * 16 + tx];
            float4 w2 = ((const float4*)Wsm)[(4 * k4 + 2) * 16 + tx];
            float4 w3 = ((const float4*)Wsm)[(4 * k4 + 3) * 16 + tx];
            #pragma unroll
            for (int i = 0; i < 8; i++) {
                float4 a = ((const float4*)As)[(8 * ty + i) * 16 + k4];
                acc[i].x += a.x * w0.x; acc[i].y += a.x * w0.y;
                acc[i].z += a.x * w0.z; acc[i].w += a.x * w0.w;
                acc[i].x += a.y * w1.x; acc[i].y += a.y * w1.y;
                acc[i].z += a.y * w1.z; acc[i].w += a.y * w1.w;
                acc[i].x += a.z * w2.x; acc[i].y += a.z * w2.y;
                acc[i].z += a.z * w2.z; acc[i].w += a.z * w2.w;
                acc[i].x += a.w * w3.x; acc[i].y += a.w * w3.y;
                acc[i].z += a.w * w3.z; acc[i].w += a.w * w3.w;
            }
        }
        __syncthreads();
    }

    float4 cv = *(const float4*)(s_c + 4 * tx);
    float4 ls = {0,0,0,0}, lq = {0,0,0,0};
    #pragma unroll
    for (int i = 0; i < 8; i++) {
        int gr = rowBase + 8 * ty + i;
        if (gr >= Nn) continue;
        float4 v = acc[i];
        v.x += cv.x; v.y += cv.y; v.z += cv.z; v.w += cv.w;
        if (FEAT) {
            v.x = fmaxf(v.x, 0.f); v.y = fmaxf(v.y, 0.f);
            v.z = fmaxf(v.z, 0.f); v.w = fmaxf(v.w, 0.f);
            *(float4*)(g_h + (long)gr * 64 + 4 * tx) = v;
            ls.x += v.x; ls.y += v.y; ls.z += v.z; ls.w += v.w;
            lq.x += v.x * v.x; lq.y += v.y * v.y;
            lq.z += v.z * v.z; lq.w += v.w * v.w;
        } else {
            float di = __ldg(g_dis + gr);
            __half2 p0 = __floats2half2_rn(di * v.x, di * v.y);
            __half2 p1 = __floats2half2_rn(di * v.z, di * v.w);
            uint2 u;
            u.x = *(unsigned*)&p0;
            u.y = *(unsigned*)&p1;
            *(uint2*)(g_zh + (long)gr * 64 + 4 * tx) = u;
        }
    }
    if (FEAT) {
        __syncthreads();
        ((float4*)As)[t]       = ls;
        ((float4*)As)[256 + t] = lq;
        __syncthreads();
        if (ty == 0) {
            #pragma unroll
            for (int j = 1; j < 16; j++) {
                float4 a = ((float4*)As)[j * 16 + tx];
                float4 b = ((float4*)As)[256 + j * 16 + tx];
                ls.x += a.x; ls.y += a.y; ls.z += a.z; ls.w += a.w;
                lq.x += b.x; lq.y += b.y; lq.z += b.z; lq.w += b.w;
            }
            red_add_v4(&g_sl[0][0][4 * tx], ls);
            red_add_v4(&g_sl[0][1][4 * tx], lq);
        }
    }
}

// ---------------- CSR gather aggregation (fp16 zs, pre-scaled) --------------
template <int MODE>
__global__ void __launch_bounds__(256)
gather_kernel(const float* __restrict__ bias,
              const int* __restrict__ batch,
              float* __restrict__ gout,
              float* __restrict__ ssum, float* __restrict__ ssq) {
    pdl_entry();
    const int t    = threadIdx.x;
    const int c    = t & 15;
    const int slot = t >> 4;
    const int i    = blockIdx.x * 16 + slot;

    if (MODE == 1 && blockIdx.x == 0) {
        if (t < 128) { g_sum[t] = 0.f; g_sumsq[t] = 0.f; }
        for (int j = t; j < Ll * 2 * HID; j += 256)
            ((float*)g_sl)[j] = 0.f;
    }

    float4 b4 = *(const float4*)(bias + 4 * c);
    float4 ls = {0,0,0,0}, lq = {0,0,0,0};

    if (i < Nn) {
        int st = __ldg(g_off + i), en = __ldg(g_off + i + 1);
        float di = __ldg(g_dis + i);
        const __half* zb = g_zh;
        float4 acc = h4_to_f4(__ldg((const uint2*)(zb + (long)i * 64) + c));
        int e = st;
        for (; e + 3 < en; e += 4) {
            int s0 = __ldg(g_csr + e + 0);
            int s1 = __ldg(g_csr + e + 1);
            int s2 = __ldg(g_csr + e + 2);
            int s3 = __ldg(g_csr + e + 3);
            uint2 u0 = __ldg((const uint2*)(zb + (long)s0 * 64) + c);
            uint2 u1 = __ldg((const uint2*)(zb + (long)s1 * 64) + c);
            uint2 u2 = __ldg((const uint2*)(zb + (long)s2 * 64) + c);
            uint2 u3 = __ldg((const uint2*)(zb + (long)s3 * 64) + c);
            float4 v0 = h4_to_f4(u0), v1 = h4_to_f4(u1);
            float4 v2 = h4_to_f4(u2), v3 = h4_to_f4(u3);
            acc.x += (v0.x + v1.x) + (v2.x + v3.x);
            acc.y += (v0.y + v1.y) + (v2.y + v3.y);
            acc.z += (v0.z + v1.z) + (v2.z + v3.z);
            acc.w += (v0.w + v1.w) + (v2.w + v3.w);
        }
        for (; e < en; e++) {
            int s = __ldg(g_csr + e);
            float4 v = h4_to_f4(__ldg((const uint2*)(zb + (long)s * 64) + c));
            acc.x += v.x; acc.y += v.y; acc.z += v.z; acc.w += v.w;
        }
        float4 h;
        h.x = fmaxf(di * acc.x + b4.x, 0.f);
        h.y = fmaxf(di * acc.y + b4.y, 0.f);
        h.z = fmaxf(di * acc.z + b4.z, 0.f);
        h.w = fmaxf(di * acc.w + b4.w, 0.f);
        if (MODE == 0) {
            *(float4*)(g_h + (long)i * 64 + 4 * c) = h;
            ls = h;
            lq.x = h.x * h.x; lq.y = h.y * h.y;
            lq.z = h.z * h.z; lq.w = h.w * h.w;
        } else {
            int g = __ldg(batch + i);
            red_add_v4(gout + (long)g * 64 + 4 * c, h);
        }
    }

    if (MODE == 0) {
        __shared__ float4 shS[256], shQ[256];
        shS[t] = ls; shQ[t] = lq;
        __syncthreads();
        if (slot == 0) {
            #pragma unroll
            for (int j = 1; j < 16; j++) {
                float4 a = shS[j * 16 + c], b = shQ[j * 16 + c];
                ls.x += a.x; ls.y += a.y; ls.z += a.z; ls.w += a.w;
                lq.x += b.x; lq.y += b.y; lq.z += b.z; lq.w += b.w;
            }
            red_add_v4(ssum + 4 * c, ls);
            red_add_v4(ssq + 4 * c, lq);
        }
    }
}

// ---------------- host helpers ------------------------------------------------
static float* sym(const void* s) {
    float* p = nullptr;
    cudaGetSymbolAddress((void**)&p, s);
    return p;
}

template <typename... Args>
static void launch_pdl(void (*f)(Args...), int grid, int block, size_t smem,
                       cudaStream_t st, Args... args) {
    cudaLaunchConfig_t cfg = {};
    cfg.gridDim  = dim3((unsigned)grid, 1, 1);
    cfg.blockDim = dim3((unsigned)block, 1, 1);
    cfg.dynamicSmemBytes = smem;
    cfg.stream = st;
    cudaLaunchAttribute attrs[1];
    attrs[0].id = cudaLaunchAttributeProgrammaticStreamSerialization;
    attrs[0].val.programmaticStreamSerializationAllowed = 1;
    cfg.attrs = attrs;
    cfg.numAttrs = 1;
    cudaLaunchKernelEx(&cfg, f, args...);
}

// ---------------- launch ------------------------------------------------------
extern "C" void kernel_launch(void* const* d_in, const int* in_sizes, int n_in,
                              void* d_out, int out_size) {
    const float* x         = (const float*)d_in[0];
    const int*   ei        = (const int*)d_in[1];
    const int*   src       = ei;
    const int*   dst       = ei + Ee;
    const int*   batch     = (const int*)d_in[2];
    const float* bn_feat_g = (const float*)d_in[3];
    const float* bn_feat_b = (const float*)d_in[4];
    const float* W_feat    = (const float*)d_in[5];
    const float* b_feat    = (const float*)d_in[6];
    const float* bn_g      = (const float*)d_in[7];
    const float* bn_b      = (const float*)d_in[8];
    const float* Ws        = (const float*)d_in[9];
    const float* bs        = (const float*)d_in[10];
    float* gout = (float*)d_out;

    static const size_t SM_FEAT  = (128*64 + 64*64 + 2*F_IN + 64) * 4;
    static const size_t SM_LAYER = (128*64 + 64*64 + 2*HID  + 64) * 4;

    static cudaStream_t s2 = nullptr;
    static cudaEvent_t e0 = nullptr, eDis = nullptr, eCsr = nullptr;
    static float *pH, *pSum, *pSq, *pSl;
    if (!s2) {
        cudaStreamCreateWithFlags(&s2, cudaStreamNonBlocking);
        cudaEventCreateWithFlags(&e0,   cudaEventDisableTiming);
        cudaEventCreateWithFlags(&eDis, cudaEventDisableTiming);
        cudaEventCreateWithFlags(&eCsr, cudaEventDisableTiming);
        cudaFuncSetAttribute(gemm_kernel<F_IN, true>,
            cudaFuncAttributeMaxDynamicSharedMemorySize, (int)SM_FEAT);
        cudaFuncSetAttribute(gemm_kernel<HID, false>,
            cudaFuncAttributeMaxDynamicSharedMemorySize, (int)SM_LAYER);
        pH   = sym(g_h);
        pSum = sym(g_sum);
        pSq  = sym(g_sumsq);
        pSl  = sym(g_sl);
    }

    // ---- fork: chain B (CSR build + dis) on s2 ----
    cudaEventRecord(e0, 0);
    cudaStreamWaitEvent(s2, e0, 0);
    cudaMemsetAsync(gout, 0, (size_t)Gg * HID * sizeof(float), s2);
    launch_pdl(count_kernel, EDGE_BLOCKS, 256, 0, s2, src, dst);
    launch_pdl(scan_dis_kernel, SCAN_NB, SCAN_T, 0, s2);
    cudaEventRecord(eDis, s2);                      // g_dis + g_off ready
    launch_pdl(fill_kernel, EDGE_BLOCKS, 256, 0, s2, src, dst);
    cudaEventRecord(eCsr, s2);                      // g_csr (+gout=0) ready

    // ---- chain A on main stream ----
    launch_pdl(stats_x_kernel, STAT_BLOCKS, 256, 0, (cudaStream_t)0, x);
    launch_pdl(gemm_kernel<F_IN, true>, GEMM_BLOCKS, 256, SM_FEAT,
               (cudaStream_t)0,
               x, bn_feat_g, bn_feat_b, W_feat, b_feat,
               (const float*)pSum, (const float*)pSq);

    for (int i = 0; i < Ll; i++) {
        float* slot = pSl + (size_t)i * 2 * HID;
        if (i == 0) cudaStreamWaitEvent(0, eDis, 0);   // epilogue needs dis
        launch_pdl(gemm_kernel<HID, false>, GEMM_BLOCKS, 256, SM_LAYER,
                   (cudaStream_t)0,
                   (const float*)pH, bn_g + i * HID, bn_b + i * HID,
                   Ws + (long)i * HID * HID, (const float*)nullptr,
                   (const float*)slot, (const float*)(slot + HID));
        if (i == 0) cudaStreamWaitEvent(0, eCsr, 0);   // gather needs CSR
        float* next = pSl + (size_t)(i + 1) * 2 * HID;
        if (i < Ll - 1)
            launch_pdl(gather_kernel<0>, GATHER_GRID, 256, 0,
                       (cudaStream_t)0,
                       bs + i * HID, (const int*)nullptr, (float*)nullptr,
                       next, next + HID);
        else
            launch_pdl(gather_kernel<1>, GATHER_GRID, 256, 0,
                       (cudaStream_t)0,
                       bs + i * HID, batch, gout,
                       (float*)nullptr, (float*)nullptr);
    }
}